// round 16
// baseline (speedup 1.0000x reference)
#include <cuda_runtime.h>
#include <cuda_fp16.h>
#include <cstdint>

// ---------------- scratch (fp16, single plane) ----------------
#define XT_N (32ll * 1024 * 256)
#define QK_N (32ll * 1024 * 512)
#define VT_N (32ll * 256 * 1024)
#define AO_N (32ll * 1024 * 256)
#define WQ_N (768ll * 256)
#define WO_N (256ll * 256)

__device__ __half g_xt[XT_N];
__device__ __half g_qk[QK_N];
__device__ __half g_vt[VT_N];
__device__ __half g_ao[AO_N];
__device__ __half g_wq[WQ_N];
__device__ __half g_wo[WO_N];

__device__ __forceinline__ uint32_t smem_u32(const void* p) {
    uint32_t a;
    asm("{ .reg .u64 t; cvta.to.shared.u64 t, %1; cvt.u32.u64 %0, t; }" : "=r"(a) : "l"(p));
    return a;
}

#define CP_ASYNC16(dst, src) \
    asm volatile("cp.async.cg.shared.global [%0], [%1], 16;" :: "r"(dst), "l"(src))
#define CP_COMMIT() asm volatile("cp.async.commit_group;")
#define CP_WAIT(n)  asm volatile("cp.async.wait_group %0;" :: "n"(n))

#define LDSM4(r0, r1, r2, r3, addr)                                               \
    asm volatile("ldmatrix.sync.aligned.m8n8.x4.shared.b16 {%0,%1,%2,%3}, [%4];"  \
                 : "=r"(r0), "=r"(r1), "=r"(r2), "=r"(r3) : "r"(addr))

#define MMA16816(c, a, b0, b1)                                                    \
    asm volatile("mma.sync.aligned.m16n8k16.row.col.f32.f16.f16.f32 "             \
                 "{%0,%1,%2,%3},{%4,%5,%6,%7},{%8,%9},{%0,%1,%2,%3};"             \
                 : "+f"((c)[0]), "+f"((c)[1]), "+f"((c)[2]), "+f"((c)[3])         \
                 : "r"((a)[0]), "r"((a)[1]), "r"((a)[2]), "r"((a)[3]),            \
                   "r"(b0), "r"(b1))

// Tile chunks: rows x 32 halves = 64 B/row, XOR-swizzled 16B granules.
__device__ __forceinline__ uint32_t sws(int row, int khalf) {
    return (uint32_t)(row * 64 + ((((khalf >> 3) ^ (row >> 1)) & 3) << 4));
}

// ======================= generic hgemm (QKV / out-proj) =======================
#define TILE_B   8192
#define OFF_A    0
#define OFF_B    8192
#define BUF_B    16384
#define NSTAGE   3
#define SMEM_BYTES (NSTAGE * BUF_B)        // 49152 B

template<int K, int LDA, int LDB, int LDC,
         long long SA, long long SB, long long SC,
         bool HAS_BIAS, bool OUT_F32, bool OUT_HALF, bool QKV>
__global__ __launch_bounds__(256, 2) void hgemm(
    const __half* __restrict__ Ah, const __half* __restrict__ Bh,
    float* __restrict__ C32, __half* __restrict__ Ch, __half* __restrict__ VTh,
    const float* __restrict__ bias_n)
{
    extern __shared__ char smem[];
    const uint32_t sbase = smem_u32(smem);
    const int tid = threadIdx.x;
    const int wid = tid >> 5, lane = tid & 31;
    const int bz = blockIdx.z;
    const int n0 = blockIdx.x * 128, m0 = blockIdx.y * 128;
    const int warp_m = wid & 1, warp_n = wid >> 1;

    const __half* Ahb = Ah + bz * SA + (long long)m0 * LDA;
    const __half* Bhb = Bh + bz * SB + (long long)n0 * LDB;

    float acc[4][4][4];
#pragma unroll
    for (int mt = 0; mt < 4; mt++)
#pragma unroll
        for (int nt = 0; nt < 4; nt++)
#pragma unroll
            for (int r = 0; r < 4; r++) acc[mt][nt][r] = 0.f;

    auto CP_TILES = [&](int ch, int buf) {
        const int k0 = ch << 5;
        const uint32_t sb = sbase + buf * BUF_B;
#pragma unroll
        for (int i = 0; i < 2; i++) {
            const int c = tid + i * 256;
            const int row = c >> 2, part = c & 3;
            const uint32_t doff = sws(row, part << 3);
            CP_ASYNC16(sb + OFF_A + doff, Ahb + (long long)row * LDA + k0 + part * 8);
            CP_ASYNC16(sb + OFF_B + doff, Bhb + (long long)row * LDB + k0 + part * 8);
        }
    };

    const int a_row = warp_m * 64 + (lane & 7) + ((lane >> 3) & 1) * 8;
    const int a_kq  = (lane >> 4) * 8;
    const int b_row = warp_n * 32 + (lane >> 4) * 8 + (lane & 7);
    const int b_kq  = ((lane >> 3) & 1) * 8;

    auto COMPUTE = [&](int buf) {
        const uint32_t o = sbase + buf * BUF_B;
#pragma unroll
        for (int s = 0; s < 2; s++) {
            uint32_t bh[8];
#pragma unroll
            for (int p = 0; p < 2; p++) {
                const int row = b_row + p * 16;
                LDSM4(bh[p * 4 + 0], bh[p * 4 + 1], bh[p * 4 + 2], bh[p * 4 + 3],
                      o + OFF_B + sws(row, s * 16 + b_kq));
            }
#pragma unroll
            for (int mt = 0; mt < 4; mt++) {
                uint32_t ah[4];
                LDSM4(ah[0], ah[1], ah[2], ah[3],
                      o + OFF_A + sws(a_row + mt * 16, s * 16 + a_kq));
#pragma unroll
                for (int nt = 0; nt < 4; nt++) {
                    const int i0 = (nt >> 1) * 4 + (nt & 1) * 2;
                    MMA16816(acc[mt][nt], ah, bh[i0], bh[i0 + 1]);
                }
            }
        }
    };

    constexpr int nch = K >> 5;
    CP_TILES(0, 0); CP_COMMIT();
    CP_TILES(1, 1); CP_COMMIT();
    int buf = 0, nxt = 2;
    for (int ch = 0; ch < nch; ch++) {
        if (ch + 1 < nch) { CP_WAIT(1); } else { CP_WAIT(0); }
        __syncthreads();
        if (ch + 2 < nch) {
            CP_TILES(ch + 2, nxt);
            CP_COMMIT();
        }
        COMPUTE(buf);
        buf = (buf + 1 == NSTAGE) ? 0 : buf + 1;
        nxt = (nxt + 1 == NSTAGE) ? 0 : nxt + 1;
    }

    const int gid = lane >> 2, q4 = lane & 3;
    const bool vmode = QKV && (n0 >= 512);

    if (!vmode) {
        float* C32b = OUT_F32 ? (C32 + bz * SC) : nullptr;
        __half* Chb = OUT_HALF ? (Ch + bz * SC) : nullptr;
#pragma unroll
        for (int mt = 0; mt < 4; mt++) {
#pragma unroll
            for (int nt = 0; nt < 4; nt++) {
                const int col = n0 + warp_n * 32 + nt * 8 + q4 * 2;
                float b0 = 0.f, b1 = 0.f;
                if (HAS_BIAS) { b0 = bias_n[col]; b1 = bias_n[col + 1]; }
#pragma unroll
                for (int h = 0; h < 2; h++) {
                    const int row = m0 + warp_m * 64 + mt * 16 + gid + h * 8;
                    float v0 = acc[mt][nt][h * 2 + 0] + b0;
                    float v1 = acc[mt][nt][h * 2 + 1] + b1;
                    if (OUT_F32)
                        *reinterpret_cast<float2*>(C32b + (long long)row * LDC + col) =
                            make_float2(v0, v1);
                    if (OUT_HALF)
                        *reinterpret_cast<__half2*>(Chb + (long long)row * LDC + col) =
                            __floats2half2_rn(v0, v1);
                }
            }
        }
    } else {
        __syncthreads();
        __half* sh = reinterpret_cast<__half*>(smem);          // [128 d][136]
#pragma unroll
        for (int mt = 0; mt < 4; mt++) {
#pragma unroll
            for (int nt = 0; nt < 4; nt++) {
                const int cl0 = warp_n * 32 + nt * 8 + q4 * 2;
                const float b0 = bias_n[n0 + cl0];
                const float b1 = bias_n[n0 + cl0 + 1];
#pragma unroll
                for (int h = 0; h < 2; h++) {
                    const int rl = warp_m * 64 + mt * 16 + gid + h * 8;
                    sh[cl0 * 136 + rl] = __float2half_rn(acc[mt][nt][h * 2 + 0] + b0);
                    sh[(cl0 + 1) * 136 + rl] = __float2half_rn(acc[mt][nt][h * 2 + 1] + b1);
                }
            }
        }
        __syncthreads();
        __half* VThb = VTh + bz * (256ll * 1024);
#pragma unroll
        for (int i = tid; i < 128 * 16; i += 256) {
            const int d = i >> 4, seg = i & 15;
            uint4 uh = *reinterpret_cast<const uint4*>(&sh[d * 136 + seg * 8]);
            const long long o2 = (long long)(n0 - 512 + d) * 1024 + m0 + seg * 8;
            *reinterpret_cast<uint4*>(&VThb[o2]) = uh;
        }
    }
}

// ======================= fused attention (4-stage, 32-key tiles) ==========
// CTA = 128 queries; Q resident (64KB); K/V in 32-key stages (32KB x 4).
// One barrier per iteration; stage being filled is 4 behind the one computed.
#define ATT_Q_OFF   0
#define ATT_STG_OFF 65536
#define ATT_STG_B   32768
#define ATT_SMEM    (65536 + 4 * 32768)   // 196608

__global__ __launch_bounds__(256, 1) void attn_kernel(
    const __half* __restrict__ qk,   // (bc, 1024, 512): Q cols 0..255, K cols 256..511
    const __half* __restrict__ vt,   // (bc, 256, 1024)
    __half* __restrict__ ao,         // (bc, 1024, 256)
    const int* __restrict__ mask)    // (bc, 1024, 1024)
{
    extern __shared__ char smem[];
    const uint32_t sb = smem_u32(smem);
    const int tid = threadIdx.x, wq = tid >> 5, lane = tid & 31;
    const int qt = blockIdx.x, bz = blockIdx.y;
    const int gid = lane >> 2, q4 = lane & 3;

    const __half* qkb = qk + (long long)bz * 524288;
    const __half* vtb = vt + (long long)bz * 262144;
    const int* mkb = mask + (long long)bz * 1048576;

    // ---- Q load: 8 d-chunks x (128 rows x 32 halves) ----
#pragma unroll
    for (int i = 0; i < 16; i++) {
        const int g = tid + i * 256;
        const int ch = g >> 9, rem = g & 511, row = rem >> 2, part = rem & 3;
        CP_ASYNC16(sb + ATT_Q_OFF + ch * 8192 + sws(row, part * 8),
                   qkb + (long long)(qt * 128 + row) * 512 + ch * 32 + part * 8);
    }

    // stage: K = 8 d-chunks x (32 rows x 32 halves) at +0 (16KB);
    //        V = 256 d-rows x 32 keys at +16384 (16KB)
    auto LOAD_KV = [&](int kt, int stg) {
        const uint32_t so = sb + ATT_STG_OFF + stg * ATT_STG_B;
#pragma unroll
        for (int i = 0; i < 8; i++) {
            const int g = tid + i * 256;              // 0..2047
            if (g < 1024) {
                const int ch = g >> 7, rem = g & 127, row = rem >> 2, part = rem & 3;
                CP_ASYNC16(so + ch * 2048 + sws(row, part * 8),
                           qkb + (long long)(kt * 32 + row) * 512 + 256 + ch * 32 + part * 8);
            } else {
                const int g2 = g - 1024;
                const int row = g2 >> 2, part = g2 & 3;
                CP_ASYNC16(so + 16384 + sws(row, part * 8),
                           vtb + (long long)row * 1024 + kt * 32 + part * 8);
            }
        }
    };
    LOAD_KV(0, 0); CP_COMMIT();      // group 0 includes Q
    LOAD_KV(1, 1); CP_COMMIT();
    LOAD_KV(2, 2); CP_COMMIT();

    float O[32][4];
#pragma unroll
    for (int i = 0; i < 32; i++)
#pragma unroll
        for (int j = 0; j < 4; j++) O[i][j] = 0.f;
    float rs0 = 0.f, rs1 = 0.f;

    const int arow = wq * 16 + (lane & 7) + ((lane >> 3) & 1) * 8;
    const int akq  = (lane >> 4) * 8;
    const int brow8 = (lane >> 4) * 8 + (lane & 7);
    const int bkq  = ((lane >> 3) & 1) * 8;
    const long long mrow0 = (long long)(qt * 128 + wq * 16 + gid) * 1024;

    for (int kt = 0; kt < 32; kt++) {
        if (kt + 2 < 32) { CP_WAIT(2); }
        else if (kt + 1 < 32) { CP_WAIT(1); }
        else { CP_WAIT(0); }
        __syncthreads();
        if (kt + 3 < 32) { LOAD_KV(kt + 3, (kt + 3) & 3); CP_COMMIT(); }

        const uint32_t so = sb + ATT_STG_OFF + (kt & 3) * ATT_STG_B;

        // mask prefetch (independent of MMAs below -> latency hidden)
        int2 mv[8];
        const int kb0 = kt * 32;
#pragma unroll
        for (int nt = 0; nt < 4; nt++) {
            const int col = kb0 + nt * 8 + q4 * 2;
            mv[nt * 2]     = *reinterpret_cast<const int2*>(mkb + mrow0 + col);
            mv[nt * 2 + 1] = *reinterpret_cast<const int2*>(mkb + mrow0 + 8192 + col);
        }
        // S = Q . K^T  (16 q x 32 k per warp)
        float s[4][4];
#pragma unroll
        for (int nt = 0; nt < 4; nt++)
#pragma unroll
            for (int j = 0; j < 4; j++) s[nt][j] = 0.f;
#pragma unroll
        for (int dch = 0; dch < 8; dch++) {
#pragma unroll
            for (int st = 0; st < 2; st++) {
                uint32_t aq[4];
                LDSM4(aq[0], aq[1], aq[2], aq[3],
                      sb + ATT_Q_OFF + dch * 8192 + sws(arow, st * 16 + akq));
                uint32_t bh[8];
#pragma unroll
                for (int kb = 0; kb < 2; kb++) {
                    const int krow = kb * 16 + brow8;
                    LDSM4(bh[kb * 4], bh[kb * 4 + 1], bh[kb * 4 + 2], bh[kb * 4 + 3],
                          so + dch * 2048 + sws(krow, st * 16 + bkq));
                }
#pragma unroll
                for (int nt = 0; nt < 4; nt++) {
                    const int i0 = (nt >> 1) * 4 + (nt & 1) * 2;
                    MMA16816(s[nt], aq, bh[i0], bh[i0 + 1]);
                }
            }
        }
        // mask -> exp -> rowsum -> repack to A-fragments
        uint32_t eA[2][4];
#pragma unroll
        for (int half = 0; half < 2; half++) {
#pragma unroll
            for (int j = 0; j < 2; j++) {
                const int nt = half * 2 + j;
                const float e0 = mv[nt * 2].x     ? 0.f : __expf(s[nt][0] * 0.0625f);
                const float e1 = mv[nt * 2].y     ? 0.f : __expf(s[nt][1] * 0.0625f);
                const float e2 = mv[nt * 2 + 1].x ? 0.f : __expf(s[nt][2] * 0.0625f);
                const float e3 = mv[nt * 2 + 1].y ? 0.f : __expf(s[nt][3] * 0.0625f);
                rs0 += e0 + e1;
                rs1 += e2 + e3;
                __half2 h01 = __floats2half2_rn(e0, e1);
                __half2 h23 = __floats2half2_rn(e2, e3);
                eA[half][j * 2]     = *reinterpret_cast<uint32_t*>(&h01);
                eA[half][j * 2 + 1] = *reinterpret_cast<uint32_t*>(&h23);
            }
        }
        // O += E . V   (16 q x 256 d, k = 32 keys)
#pragma unroll
        for (int dblk = 0; dblk < 16; dblk++) {
#pragma unroll
            for (int kstep = 0; kstep < 2; kstep++) {
                uint32_t bv[4];
                LDSM4(bv[0], bv[1], bv[2], bv[3],
                      so + 16384 + sws(dblk * 16 + brow8, kstep * 16 + bkq));
                MMA16816(O[dblk * 2],     eA[kstep], bv[0], bv[1]);
                MMA16816(O[dblk * 2 + 1], eA[kstep], bv[2], bv[3]);
            }
        }
    }

    // ---- epilogue: rowsum reduce, normalize, store fp16 ----
    rs0 += __shfl_xor_sync(0xffffffffu, rs0, 1);
    rs0 += __shfl_xor_sync(0xffffffffu, rs0, 2);
    rs1 += __shfl_xor_sync(0xffffffffu, rs1, 1);
    rs1 += __shfl_xor_sync(0xffffffffu, rs1, 2);
    const float inv0 = __frcp_rn(rs0), inv1 = __frcp_rn(rs1);

    __half* aob = ao + (long long)bz * 262144 + (long long)(qt * 128 + wq * 16 + gid) * 256;
#pragma unroll
    for (int nt = 0; nt < 32; nt++) {
        const int col = nt * 8 + q4 * 2;
        *reinterpret_cast<__half2*>(aob + col) =
            __floats2half2_rn(O[nt][0] * inv0, O[nt][1] * inv0);
        *reinterpret_cast<__half2*>(aob + 8 * 256 + col) =
            __floats2half2_rn(O[nt][2] * inv1, O[nt][3] * inv1);
    }
}

// ---------------- transpose x: (bc, 256, 1024) -> (bc, 1024, 256) fp16 ----------
__global__ __launch_bounds__(256) void transpose_kernel(
    const float* __restrict__ x, __half* __restrict__ xh)
{
    __shared__ float tile[32][33];
    const int bz = blockIdx.z;
    const float* xs = x + (long long)bz * 256 * 1024;
    __half* xhd = xh + (long long)bz * 1024 * 256;
    const int t0 = blockIdx.x * 32, d0 = blockIdx.y * 32;
    const int tx = threadIdx.x, ty = threadIdx.y;
#pragma unroll
    for (int k = 0; k < 4; k++)
        tile[ty + k * 8][tx] = xs[(long long)(d0 + ty + k * 8) * 1024 + t0 + tx];
    __syncthreads();
#pragma unroll
    for (int k = 0; k < 4; k++)
        xhd[(long long)(t0 + ty + k * 8) * 256 + d0 + tx] =
            __float2half_rn(tile[tx][ty + k * 8]);
}

// ---------------- weight fp32 -> fp16 ----------------
__global__ void cvt_kernel(const float* __restrict__ w, __half* __restrict__ h, int n)
{
    int i = blockIdx.x * 256 + threadIdx.x;
    if (i < n) h[i] = __float2half_rn(w[i]);
}

extern "C" void kernel_launch(void* const* d_in, const int* in_sizes, int n_in,
                              void* d_out, int out_size)
{
    const float* x     = (const float*)d_in[0];   // (8,4,256,1024)
    const int*   mask  = (const int*)d_in[1];     // (8,4,1024,1024) bool -> int32
    const float* w_qkv = (const float*)d_in[2];   // (768,256)
    const float* b_qkv = (const float*)d_in[3];   // (768,)
    const float* w_out = (const float*)d_in[4];   // (256,256)
    const float* b_out = (const float*)d_in[5];   // (256,)
    float*       out   = (float*)d_out;           // (8,4,1024,256)

    __half *xt, *qk, *vt, *ao, *wq, *wo;
    cudaGetSymbolAddress((void**)&xt, g_xt);
    cudaGetSymbolAddress((void**)&qk, g_qk);
    cudaGetSymbolAddress((void**)&vt, g_vt);
    cudaGetSymbolAddress((void**)&ao, g_ao);
    cudaGetSymbolAddress((void**)&wq, g_wq);
    cudaGetSymbolAddress((void**)&wo, g_wo);

    // 0) converters
    transpose_kernel<<<dim3(32, 8, 32), dim3(32, 8)>>>(x, xt);
    cvt_kernel<<<768, 256>>>(w_qkv, wq, 768 * 256);
    cvt_kernel<<<256, 256>>>(w_out, wo, 256 * 256);

    // 1) QKV: Q,K -> qk fp16; V -> vt fp16 (transposed)
    {
        auto kfn = hgemm<256, 256, 256, 512, 1024ll * 256, 0ll, 1024ll * 512,
                         true, false, true, true>;
        cudaFuncSetAttribute(kfn, cudaFuncAttributeMaxDynamicSharedMemorySize, SMEM_BYTES);
        kfn<<<dim3(6, 8, 32), 256, SMEM_BYTES>>>(
            xt, wq, nullptr, qk, vt, b_qkv);
    }

    // 2) fused attention: ao = softmax(mask(QK^T/16)) @ V   (fp16)
    cudaFuncSetAttribute(attn_kernel, cudaFuncAttributeMaxDynamicSharedMemorySize, ATT_SMEM);
    attn_kernel<<<dim3(8, 32), 256, ATT_SMEM>>>(qk, vt, ao, mask);

    // 3) out (fp32) = ao @ w_out^T + b_out
    {
        auto kfn = hgemm<256, 256, 256, 256, 1024ll * 256, 0ll, 1024ll * 256,
                         true, true, false, false>;
        cudaFuncSetAttribute(kfn, cudaFuncAttributeMaxDynamicSharedMemorySize, SMEM_BYTES);
        kfn<<<dim3(2, 8, 32), 256, SMEM_BYTES>>>(
            ao, wo, out, nullptr, nullptr, b_out);
    }
}

// round 17
// speedup vs baseline: 1.0615x; 1.0615x over previous
#include <cuda_runtime.h>
#include <cuda_fp16.h>
#include <cstdint>

// ---------------- scratch (fp16, single plane) ----------------
#define XT_N (32ll * 1024 * 256)
#define QK_N (32ll * 1024 * 512)
#define VT_N (32ll * 256 * 1024)
#define AO_N (32ll * 1024 * 256)
#define WQ_N (768ll * 256)
#define WO_N (256ll * 256)

__device__ __half g_xt[XT_N];
__device__ __half g_qk[QK_N];
__device__ __half g_vt[VT_N];
__device__ __half g_ao[AO_N];
__device__ __half g_wq[WQ_N];
__device__ __half g_wo[WO_N];

__device__ __forceinline__ uint32_t smem_u32(const void* p) {
    uint32_t a;
    asm("{ .reg .u64 t; cvta.to.shared.u64 t, %1; cvt.u32.u64 %0, t; }" : "=r"(a) : "l"(p));
    return a;
}

#define CP_ASYNC16(dst, src) \
    asm volatile("cp.async.cg.shared.global [%0], [%1], 16;" :: "r"(dst), "l"(src))
#define CP_COMMIT() asm volatile("cp.async.commit_group;")
#define CP_WAIT(n)  asm volatile("cp.async.wait_group %0;" :: "n"(n))

#define LDSM4(r0, r1, r2, r3, addr)                                               \
    asm volatile("ldmatrix.sync.aligned.m8n8.x4.shared.b16 {%0,%1,%2,%3}, [%4];"  \
                 : "=r"(r0), "=r"(r1), "=r"(r2), "=r"(r3) : "r"(addr))

#define MMA16816(c, a, b0, b1)                                                    \
    asm volatile("mma.sync.aligned.m16n8k16.row.col.f32.f16.f16.f32 "             \
                 "{%0,%1,%2,%3},{%4,%5,%6,%7},{%8,%9},{%0,%1,%2,%3};"             \
                 : "+f"((c)[0]), "+f"((c)[1]), "+f"((c)[2]), "+f"((c)[3])         \
                 : "r"((a)[0]), "r"((a)[1]), "r"((a)[2]), "r"((a)[3]),            \
                   "r"(b0), "r"(b1))

// Tile chunks: rows x 32 halves = 64 B/row, XOR-swizzled 16B granules.
__device__ __forceinline__ uint32_t sws(int row, int khalf) {
    return (uint32_t)(row * 64 + ((((khalf >> 3) ^ (row >> 1)) & 3) << 4));
}

// ======================= generic hgemm (QKV / out-proj) =======================
#define TILE_B   8192
#define OFF_A    0
#define OFF_B    8192
#define BUF_B    16384
#define NSTAGE   3
#define SMEM_BYTES (NSTAGE * BUF_B)        // 49152 B

template<int K, int LDA, int LDB, int LDC,
         long long SA, long long SB, long long SC,
         bool HAS_BIAS, bool OUT_F32, bool OUT_HALF, bool QKV>
__global__ __launch_bounds__(256, 2) void hgemm(
    const __half* __restrict__ Ah, const __half* __restrict__ Bh,
    float* __restrict__ C32, __half* __restrict__ Ch, __half* __restrict__ VTh,
    const float* __restrict__ bias_n)
{
    extern __shared__ char smem[];
    const uint32_t sbase = smem_u32(smem);
    const int tid = threadIdx.x;
    const int wid = tid >> 5, lane = tid & 31;
    const int bz = blockIdx.z;
    const int n0 = blockIdx.x * 128, m0 = blockIdx.y * 128;
    const int warp_m = wid & 1, warp_n = wid >> 1;

    const __half* Ahb = Ah + bz * SA + (long long)m0 * LDA;
    const __half* Bhb = Bh + bz * SB + (long long)n0 * LDB;

    float acc[4][4][4];
#pragma unroll
    for (int mt = 0; mt < 4; mt++)
#pragma unroll
        for (int nt = 0; nt < 4; nt++)
#pragma unroll
            for (int r = 0; r < 4; r++) acc[mt][nt][r] = 0.f;

    auto CP_TILES = [&](int ch, int buf) {
        const int k0 = ch << 5;
        const uint32_t sb = sbase + buf * BUF_B;
#pragma unroll
        for (int i = 0; i < 2; i++) {
            const int c = tid + i * 256;
            const int row = c >> 2, part = c & 3;
            const uint32_t doff = sws(row, part << 3);
            CP_ASYNC16(sb + OFF_A + doff, Ahb + (long long)row * LDA + k0 + part * 8);
            CP_ASYNC16(sb + OFF_B + doff, Bhb + (long long)row * LDB + k0 + part * 8);
        }
    };

    const int a_row = warp_m * 64 + (lane & 7) + ((lane >> 3) & 1) * 8;
    const int a_kq  = (lane >> 4) * 8;
    const int b_row = warp_n * 32 + (lane >> 4) * 8 + (lane & 7);
    const int b_kq  = ((lane >> 3) & 1) * 8;

    auto COMPUTE = [&](int buf) {
        const uint32_t o = sbase + buf * BUF_B;
#pragma unroll
        for (int s = 0; s < 2; s++) {
            uint32_t bh[8];
#pragma unroll
            for (int p = 0; p < 2; p++) {
                const int row = b_row + p * 16;
                LDSM4(bh[p * 4 + 0], bh[p * 4 + 1], bh[p * 4 + 2], bh[p * 4 + 3],
                      o + OFF_B + sws(row, s * 16 + b_kq));
            }
#pragma unroll
            for (int mt = 0; mt < 4; mt++) {
                uint32_t ah[4];
                LDSM4(ah[0], ah[1], ah[2], ah[3],
                      o + OFF_A + sws(a_row + mt * 16, s * 16 + a_kq));
#pragma unroll
                for (int nt = 0; nt < 4; nt++) {
                    const int i0 = (nt >> 1) * 4 + (nt & 1) * 2;
                    MMA16816(acc[mt][nt], ah, bh[i0], bh[i0 + 1]);
                }
            }
        }
    };

    constexpr int nch = K >> 5;
    CP_TILES(0, 0); CP_COMMIT();
    CP_TILES(1, 1); CP_COMMIT();
    int buf = 0, nxt = 2;
    for (int ch = 0; ch < nch; ch++) {
        if (ch + 1 < nch) { CP_WAIT(1); } else { CP_WAIT(0); }
        __syncthreads();
        if (ch + 2 < nch) {
            CP_TILES(ch + 2, nxt);
            CP_COMMIT();
        }
        COMPUTE(buf);
        buf = (buf + 1 == NSTAGE) ? 0 : buf + 1;
        nxt = (nxt + 1 == NSTAGE) ? 0 : nxt + 1;
    }

    const int gid = lane >> 2, q4 = lane & 3;
    const bool vmode = QKV && (n0 >= 512);

    if (!vmode) {
        float* C32b = OUT_F32 ? (C32 + bz * SC) : nullptr;
        __half* Chb = OUT_HALF ? (Ch + bz * SC) : nullptr;
#pragma unroll
        for (int mt = 0; mt < 4; mt++) {
#pragma unroll
            for (int nt = 0; nt < 4; nt++) {
                const int col = n0 + warp_n * 32 + nt * 8 + q4 * 2;
                float b0 = 0.f, b1 = 0.f;
                if (HAS_BIAS) { b0 = bias_n[col]; b1 = bias_n[col + 1]; }
#pragma unroll
                for (int h = 0; h < 2; h++) {
                    const int row = m0 + warp_m * 64 + mt * 16 + gid + h * 8;
                    float v0 = acc[mt][nt][h * 2 + 0] + b0;
                    float v1 = acc[mt][nt][h * 2 + 1] + b1;
                    if (OUT_F32)
                        *reinterpret_cast<float2*>(C32b + (long long)row * LDC + col) =
                            make_float2(v0, v1);
                    if (OUT_HALF)
                        *reinterpret_cast<__half2*>(Chb + (long long)row * LDC + col) =
                            __floats2half2_rn(v0, v1);
                }
            }
        }
    } else {
        __syncthreads();
        __half* sh = reinterpret_cast<__half*>(smem);          // [128 d][136]
#pragma unroll
        for (int mt = 0; mt < 4; mt++) {
#pragma unroll
            for (int nt = 0; nt < 4; nt++) {
                const int cl0 = warp_n * 32 + nt * 8 + q4 * 2;
                const float b0 = bias_n[n0 + cl0];
                const float b1 = bias_n[n0 + cl0 + 1];
#pragma unroll
                for (int h = 0; h < 2; h++) {
                    const int rl = warp_m * 64 + mt * 16 + gid + h * 8;
                    sh[cl0 * 136 + rl] = __float2half_rn(acc[mt][nt][h * 2 + 0] + b0);
                    sh[(cl0 + 1) * 136 + rl] = __float2half_rn(acc[mt][nt][h * 2 + 1] + b1);
                }
            }
        }
        __syncthreads();
        __half* VThb = VTh + bz * (256ll * 1024);
#pragma unroll
        for (int i = tid; i < 128 * 16; i += 256) {
            const int d = i >> 4, seg = i & 15;
            uint4 uh = *reinterpret_cast<const uint4*>(&sh[d * 136 + seg * 8]);
            const long long o2 = (long long)(n0 - 512 + d) * 1024 + m0 + seg * 8;
            *reinterpret_cast<uint4*>(&VThb[o2]) = uh;
        }
    }
}

// ======================= fused attention (2-stage, 64-key tiles) ==========
// CTA = 128 queries; Q resident (64KB); K/V double-buffered 64KB stages.
// ks-blocks software-pipelined: S0,S1 issued before exp0 so MUFU chains
// overlap tensor-pipe drain; EV0 overlaps exp1.
#define ATT_Q_OFF   0
#define ATT_STG_OFF 65536
#define ATT_STG_B   65536
#define ATT_SMEM    (65536 + 2 * 65536)   // 196608

__global__ __launch_bounds__(256, 1) void attn_kernel(
    const __half* __restrict__ qk,   // (bc, 1024, 512): Q cols 0..255, K cols 256..511
    const __half* __restrict__ vt,   // (bc, 256, 1024)
    __half* __restrict__ ao,         // (bc, 1024, 256)
    const int* __restrict__ mask)    // (bc, 1024, 1024)
{
    extern __shared__ char smem[];
    const uint32_t sb = smem_u32(smem);
    const int tid = threadIdx.x, wq = tid >> 5, lane = tid & 31;
    const int qt = blockIdx.x, bz = blockIdx.y;
    const int gid = lane >> 2, q4 = lane & 3;

    const __half* qkb = qk + (long long)bz * 524288;
    const __half* vtb = vt + (long long)bz * 262144;
    const int* mkb = mask + (long long)bz * 1048576;

    // ---- Q load: 8 d-chunks x (128 rows x 32 halves) ----
#pragma unroll
    for (int i = 0; i < 16; i++) {
        const int g = tid + i * 256;
        const int ch = g >> 9, rem = g & 511, row = rem >> 2, part = rem & 3;
        CP_ASYNC16(sb + ATT_Q_OFF + ch * 8192 + sws(row, part * 8),
                   qkb + (long long)(qt * 128 + row) * 512 + ch * 32 + part * 8);
    }

    // K tile: 8 d-chunks x (64 rows x 32 halves) at +0; V tile: 2 t-chunks x (256 x 32) at +32768
    auto LOAD_KV = [&](int kt, int stg) {
        const uint32_t so = sb + ATT_STG_OFF + stg * ATT_STG_B;
#pragma unroll
        for (int i = 0; i < 16; i++) {
            const int g = tid + i * 256;
            if (g < 2048) {
                const int ch = g >> 8, rem = g & 255, row = rem >> 2, part = rem & 3;
                CP_ASYNC16(so + ch * 4096 + sws(row, part * 8),
                           qkb + (long long)(kt * 64 + row) * 512 + 256 + ch * 32 + part * 8);
            } else {
                const int g2 = g - 2048;
                const int tc = g2 >> 10, rem = g2 & 1023, row = rem >> 2, part = rem & 3;
                CP_ASYNC16(so + 32768 + tc * 16384 + sws(row, part * 8),
                           vtb + (long long)row * 1024 + kt * 64 + tc * 32 + part * 8);
            }
        }
    };
    LOAD_KV(0, 0); CP_COMMIT();      // group includes Q
    LOAD_KV(1, 1); CP_COMMIT();

    float O[32][4];
#pragma unroll
    for (int i = 0; i < 32; i++)
#pragma unroll
        for (int j = 0; j < 4; j++) O[i][j] = 0.f;
    float rs0 = 0.f, rs1 = 0.f;

    const int arow = wq * 16 + (lane & 7) + ((lane >> 3) & 1) * 8;
    const int akq  = (lane >> 4) * 8;
    const int brow8 = (lane >> 4) * 8 + (lane & 7);
    const int bkq  = ((lane >> 3) & 1) * 8;
    const long long mrow0 = (long long)(qt * 128 + wq * 16 + gid) * 1024;

    for (int kt = 0; kt < 16; kt++) {
        if (kt + 1 < 16) { CP_WAIT(1); } else { CP_WAIT(0); }
        __syncthreads();
        const uint32_t so = sb + ATT_STG_OFF + (kt & 1) * ATT_STG_B;
        const int kb0 = kt * 64;

        // ---- mask for ks=0 (in flight under S0) ----
        int2 mv0[8];
#pragma unroll
        for (int nt = 0; nt < 4; nt++) {
            const int col = kb0 + nt * 8 + q4 * 2;
            mv0[nt * 2]     = *reinterpret_cast<const int2*>(mkb + mrow0 + col);
            mv0[nt * 2 + 1] = *reinterpret_cast<const int2*>(mkb + mrow0 + 8192 + col);
        }

        // ---- S0, S1 MMAs (back-to-back; exp of ks0 will overlap S1 drain) ----
        float s0[4][4], s1[4][4];
#pragma unroll
        for (int nt = 0; nt < 4; nt++)
#pragma unroll
            for (int j = 0; j < 4; j++) { s0[nt][j] = 0.f; s1[nt][j] = 0.f; }
#pragma unroll
        for (int ks = 0; ks < 2; ks++) {
            float (*s)[4] = ks ? s1 : s0;
#pragma unroll
            for (int dch = 0; dch < 8; dch++) {
#pragma unroll
                for (int st = 0; st < 2; st++) {
                    uint32_t aq[4];
                    LDSM4(aq[0], aq[1], aq[2], aq[3],
                          sb + ATT_Q_OFF + dch * 8192 + sws(arow, st * 16 + akq));
                    uint32_t bh[8];
#pragma unroll
                    for (int kb = 0; kb < 2; kb++) {
                        const int krow = ks * 32 + kb * 16 + brow8;
                        LDSM4(bh[kb * 4], bh[kb * 4 + 1], bh[kb * 4 + 2], bh[kb * 4 + 3],
                              so + dch * 4096 + sws(krow, st * 16 + bkq));
                    }
#pragma unroll
                    for (int nt = 0; nt < 4; nt++) {
                        const int i0 = (nt >> 1) * 4 + (nt & 1) * 2;
                        MMA16816(s[nt], aq, bh[i0], bh[i0 + 1]);
                    }
                }
            }
        }

        // ---- mask for ks=1 (latency hides under exp0/EV0) ----
        int2 mv1[8];
#pragma unroll
        for (int nt = 0; nt < 4; nt++) {
            const int col = kb0 + 32 + nt * 8 + q4 * 2;
            mv1[nt * 2]     = *reinterpret_cast<const int2*>(mkb + mrow0 + col);
            mv1[nt * 2 + 1] = *reinterpret_cast<const int2*>(mkb + mrow0 + 8192 + col);
        }

        // ---- exp0 -> eA0 ; EV0 ; exp1 -> eA1 ; EV1 ----
#pragma unroll
        for (int ks = 0; ks < 2; ks++) {
            float (*s)[4] = ks ? s1 : s0;
            int2* mv = ks ? mv1 : mv0;
            uint32_t eA[2][4];
#pragma unroll
            for (int half = 0; half < 2; half++) {
#pragma unroll
                for (int j = 0; j < 2; j++) {
                    const int nt = half * 2 + j;
                    const float e0 = mv[nt * 2].x     ? 0.f : __expf(s[nt][0] * 0.0625f);
                    const float e1 = mv[nt * 2].y     ? 0.f : __expf(s[nt][1] * 0.0625f);
                    const float e2 = mv[nt * 2 + 1].x ? 0.f : __expf(s[nt][2] * 0.0625f);
                    const float e3 = mv[nt * 2 + 1].y ? 0.f : __expf(s[nt][3] * 0.0625f);
                    rs0 += e0 + e1;
                    rs1 += e2 + e3;
                    __half2 h01 = __floats2half2_rn(e0, e1);
                    __half2 h23 = __floats2half2_rn(e2, e3);
                    eA[half][j * 2]     = *reinterpret_cast<uint32_t*>(&h01);
                    eA[half][j * 2 + 1] = *reinterpret_cast<uint32_t*>(&h23);
                }
            }
#pragma unroll
            for (int dblk = 0; dblk < 16; dblk++) {
#pragma unroll
                for (int kstep = 0; kstep < 2; kstep++) {
                    uint32_t bv[4];
                    LDSM4(bv[0], bv[1], bv[2], bv[3],
                          so + 32768 + ks * 16384 + sws(dblk * 16 + brow8, kstep * 16 + bkq));
                    MMA16816(O[dblk * 2],     eA[kstep], bv[0], bv[1]);
                    MMA16816(O[dblk * 2 + 1], eA[kstep], bv[2], bv[3]);
                }
            }
        }
        __syncthreads();
        if (kt + 2 < 16) { LOAD_KV(kt + 2, kt & 1); CP_COMMIT(); }
    }

    // ---- epilogue: rowsum reduce, normalize, store fp16 ----
    rs0 += __shfl_xor_sync(0xffffffffu, rs0, 1);
    rs0 += __shfl_xor_sync(0xffffffffu, rs0, 2);
    rs1 += __shfl_xor_sync(0xffffffffu, rs1, 1);
    rs1 += __shfl_xor_sync(0xffffffffu, rs1, 2);
    const float inv0 = __frcp_rn(rs0), inv1 = __frcp_rn(rs1);

    __half* aob = ao + (long long)bz * 262144 + (long long)(qt * 128 + wq * 16 + gid) * 256;
#pragma unroll
    for (int nt = 0; nt < 32; nt++) {
        const int col = nt * 8 + q4 * 2;
        *reinterpret_cast<__half2*>(aob + col) =
            __floats2half2_rn(O[nt][0] * inv0, O[nt][1] * inv0);
        *reinterpret_cast<__half2*>(aob + 8 * 256 + col) =
            __floats2half2_rn(O[nt][2] * inv1, O[nt][3] * inv1);
    }
}

// ---------------- transpose x: (bc, 256, 1024) -> (bc, 1024, 256) fp16 ----------
__global__ __launch_bounds__(256) void transpose_kernel(
    const float* __restrict__ x, __half* __restrict__ xh)
{
    __shared__ float tile[32][33];
    const int bz = blockIdx.z;
    const float* xs = x + (long long)bz * 256 * 1024;
    __half* xhd = xh + (long long)bz * 1024 * 256;
    const int t0 = blockIdx.x * 32, d0 = blockIdx.y * 32;
    const int tx = threadIdx.x, ty = threadIdx.y;
#pragma unroll
    for (int k = 0; k < 4; k++)
        tile[ty + k * 8][tx] = xs[(long long)(d0 + ty + k * 8) * 1024 + t0 + tx];
    __syncthreads();
#pragma unroll
    for (int k = 0; k < 4; k++)
        xhd[(long long)(t0 + ty + k * 8) * 256 + d0 + tx] =
            __float2half_rn(tile[tx][ty + k * 8]);
}

// ---------------- weight fp32 -> fp16 ----------------
__global__ void cvt_kernel(const float* __restrict__ w, __half* __restrict__ h, int n)
{
    int i = blockIdx.x * 256 + threadIdx.x;
    if (i < n) h[i] = __float2half_rn(w[i]);
}

extern "C" void kernel_launch(void* const* d_in, const int* in_sizes, int n_in,
                              void* d_out, int out_size)
{
    const float* x     = (const float*)d_in[0];   // (8,4,256,1024)
    const int*   mask  = (const int*)d_in[1];     // (8,4,1024,1024) bool -> int32
    const float* w_qkv = (const float*)d_in[2];   // (768,256)
    const float* b_qkv = (const float*)d_in[3];   // (768,)
    const float* w_out = (const float*)d_in[4];   // (256,256)
    const float* b_out = (const float*)d_in[5];   // (256,)
    float*       out   = (float*)d_out;           // (8,4,1024,256)

    __half *xt, *qk, *vt, *ao, *wq, *wo;
    cudaGetSymbolAddress((void**)&xt, g_xt);
    cudaGetSymbolAddress((void**)&qk, g_qk);
    cudaGetSymbolAddress((void**)&vt, g_vt);
    cudaGetSymbolAddress((void**)&ao, g_ao);
    cudaGetSymbolAddress((void**)&wq, g_wq);
    cudaGetSymbolAddress((void**)&wo, g_wo);

    // 0) converters
    transpose_kernel<<<dim3(32, 8, 32), dim3(32, 8)>>>(x, xt);
    cvt_kernel<<<768, 256>>>(w_qkv, wq, 768 * 256);
    cvt_kernel<<<256, 256>>>(w_out, wo, 256 * 256);

    // 1) QKV: Q,K -> qk fp16; V -> vt fp16 (transposed)
    {
        auto kfn = hgemm<256, 256, 256, 512, 1024ll * 256, 0ll, 1024ll * 512,
                         true, false, true, true>;
        cudaFuncSetAttribute(kfn, cudaFuncAttributeMaxDynamicSharedMemorySize, SMEM_BYTES);
        kfn<<<dim3(6, 8, 32), 256, SMEM_BYTES>>>(
            xt, wq, nullptr, qk, vt, b_qkv);
    }

    // 2) fused attention: ao = softmax(mask(QK^T/16)) @ V   (fp16)
    cudaFuncSetAttribute(attn_kernel, cudaFuncAttributeMaxDynamicSharedMemorySize, ATT_SMEM);
    attn_kernel<<<dim3(8, 32), 256, ATT_SMEM>>>(qk, vt, ao, mask);

    // 3) out (fp32) = ao @ w_out^T + b_out
    {
        auto kfn = hgemm<256, 256, 256, 256, 1024ll * 256, 0ll, 1024ll * 256,
                         true, true, false, false>;
        cudaFuncSetAttribute(kfn, cudaFuncAttributeMaxDynamicSharedMemorySize, SMEM_BYTES);
        kfn<<<dim3(2, 8, 32), 256, SMEM_BYTES>>>(
            ao, wo, out, nullptr, nullptr, b_out);
    }
}